// round 14
// baseline (speedup 1.0000x reference)
#include <cuda_runtime.h>
#include <cuda_fp16.h>
#include <mma.h>
#include <math.h>
#include <stdint.h>

using namespace nvcuda;

#define NN 50000
#define NP 50048      // padded rows (mult of 128)
#define NE 800000
#define F  128
#define MT 128        // rows per MMA block
#define SPAD 65       // scores transposed-tile pad
#define MMA_GRID    391
#define SCORES_GRID 782
#define AGG_GRID   6250

// ---------------- scratch (device globals; zero-initialized) ---------------
__device__ __align__(16) float  g_feat[NP * F];     // fp32 GEMM output (padded)
__device__ __align__(16) __half g_hin16[NP * F];    // fp16 copy of current h
__device__ __align__(16) __half g_W16[3][F * F];    // fp16 W per layer
__device__ __align__(16) float g_h1[NN * F];
__device__ __align__(16) float g_h2[NN * F];
__device__ __align__(16) float g_el[NN * 4];
__device__ __align__(16) float g_er[NN * 4];
__device__ __align__(16) float g_wl[3][4 * F];      // W @ al[h]
__device__ __align__(16) float g_wr[3][4 * F];      // W @ ar[h]
__device__ int g_rowptr[NN + 1];

// ---------------- wprep: wl/wr (exact fp32) + fp16 W copy ------------------
__device__ __forceinline__ void wprep_dev(
    const float* __restrict__ W, const float* __restrict__ al,
    const float* __restrict__ ar, int slot)
{
    const int tid = threadIdx.x;
    #pragma unroll
    for (int j = 0; j < 4; j++) {
        int o = tid + 256 * j;                 // 1024 outputs
        int k = o & 127, hh = o >> 7, h = hh & 3;
        const float* vec = (hh < 4) ? al : ar;
        float s = 0.f;
        #pragma unroll
        for (int d = 0; d < 32; d++)
            s = fmaf(__ldg(&W[k * F + h * 32 + d]), __ldg(&vec[h * 32 + d]), s);
        if (hh < 4) g_wl[slot][h * F + k] = s; else g_wr[slot][h * F + k] = s;
    }
    // fp16 copy of W: 16384 halfs = 4096 uint2, 16 per thread
    uint2* w16 = reinterpret_cast<uint2*>(g_W16[slot]);
    #pragma unroll
    for (int i = 0; i < 16; i++) {
        int idx = tid + 256 * i;
        float4 v = __ldg(reinterpret_cast<const float4*>(&W[idx * 4]));
        __half2 p01 = __floats2half2_rn(v.x, v.y);
        __half2 p23 = __floats2half2_rn(v.z, v.w);
        uint2 pk;
        pk.x = *reinterpret_cast<unsigned*>(&p01);
        pk.y = *reinterpret_cast<unsigned*>(&p23);
        w16[idx] = pk;
    }
}

// ---------------- rowptr + wprep0 + x->fp16 conversion ---------------------
// blocks [0,196): binary search; 196: wprep slot 0; [197, 197+782): x16.
__global__ __launch_bounds__(256) void rowptr_kernel(
    const int* __restrict__ dst, const float* __restrict__ x,
    const float* __restrict__ W0, const float* __restrict__ al0,
    const float* __restrict__ ar0)
{
    const int tid = threadIdx.x;
    if (blockIdx.x < 196) {
        int n = blockIdx.x * 256 + tid;
        if (n > NN) return;
        int lo = 0, hi = NE;
        while (lo < hi) {
            int mid = (lo + hi) >> 1;
            if (dst[mid] < n) lo = mid + 1; else hi = mid;
        }
        g_rowptr[n] = lo;
    } else if (blockIdx.x == 196) {
        wprep_dev(W0, al0, ar0, 0);
    } else {
        // convert 64 rows of x to fp16 (zero-pad rows >= NN)
        int rbase = (blockIdx.x - 197) * 64;
        uint2* h16 = reinterpret_cast<uint2*>(g_hin16);
        #pragma unroll
        for (int i = 0; i < 8; i++) {
            int idx = tid + 256 * i;           // 2048 float4 slots
            int row = rbase + (idx >> 5), c4 = idx & 31;
            uint2 pk = make_uint2(0u, 0u);
            if (row < NN) {
                float4 v = __ldg(reinterpret_cast<const float4*>(&x[row * F + 4 * c4]));
                __half2 p01 = __floats2half2_rn(v.x, v.y);
                __half2 p23 = __floats2half2_rn(v.z, v.w);
                pk.x = *reinterpret_cast<unsigned*>(&p01);
                pk.y = *reinterpret_cast<unsigned*>(&p23);
            }
            if (row < NP) h16[row * 32 + c4] = pk;
        }
    }
}

// ---------------- fused MMA (global-operand WMMA) + scores -----------------
// Blocks [0, MMA_GRID): feat tile = h16 @ W16 -> g_feat (fp32), NO smem.
// Blocks [MMA_GRID, ..): 64 rows of el/er (exact fp32) from fp32 hin.
extern __shared__ __align__(16) float s_hsT[];   // scores path only: [F][SPAD]

__global__ __launch_bounds__(256) void mma_scores_kernel(
    const float* __restrict__ hin, int slot)
{
    const int tid = threadIdx.x;

    if (blockIdx.x >= MMA_GRID) {
        // ================= scores path =================
        const int base = (blockIdx.x - MMA_GRID) * 64;
        {
            const int k4 = tid & 31, r0 = tid >> 5;
            #pragma unroll
            for (int j = 0; j < 8; j++) {
                int r = r0 + 8 * j;
                int n = base + r;
                float4 v = (n < NN)
                    ? __ldg(reinterpret_cast<const float4*>(&hin[n * F + 4 * k4]))
                    : make_float4(0.f, 0.f, 0.f, 0.f);
                s_hsT[(4 * k4 + 0) * SPAD + r] = v.x;
                s_hsT[(4 * k4 + 1) * SPAD + r] = v.y;
                s_hsT[(4 * k4 + 2) * SPAD + r] = v.z;
                s_hsT[(4 * k4 + 3) * SPAD + r] = v.w;
            }
        }
        __syncthreads();

        const int r  = tid & 63;
        const int hd = tid >> 6;
        const int n  = base + r;
        float el = 0.f, er = 0.f;
        const float4* wl4 = reinterpret_cast<const float4*>(g_wl[slot]);
        const float4* wr4 = reinterpret_cast<const float4*>(g_wr[slot]);
        #pragma unroll 8
        for (int k4 = 0; k4 < 32; k4++) {
            float4 wlv = __ldg(&wl4[hd * 32 + k4]);
            float4 wrv = __ldg(&wr4[hd * 32 + k4]);
            float h0 = s_hsT[(4 * k4 + 0) * SPAD + r];
            float h1 = s_hsT[(4 * k4 + 1) * SPAD + r];
            float h2 = s_hsT[(4 * k4 + 2) * SPAD + r];
            float h3 = s_hsT[(4 * k4 + 3) * SPAD + r];
            el = fmaf(h0, wlv.x, fmaf(h1, wlv.y, fmaf(h2, wlv.z, fmaf(h3, wlv.w, el))));
            er = fmaf(h0, wrv.x, fmaf(h1, wrv.y, fmaf(h2, wrv.z, fmaf(h3, wrv.w, er))));
        }
        if (n < NN) {
            g_el[n * 4 + hd] = el;
            g_er[n * 4 + hd] = er;
        }
        return;
    }

    // ================= MMA path (no smem, global fragments) ================
    const int base = blockIdx.x * MT;
    const int w  = tid >> 5;
    const int wr = w & 3;       // rows 32*wr .. +31
    const int wc = w >> 2;      // cols 64*wc .. +63
    const __half* A = g_hin16;
    const __half* B = g_W16[slot];

    wmma::fragment<wmma::accumulator, 16, 16, 16, float> c[2][4];
    #pragma unroll
    for (int i = 0; i < 2; i++)
        #pragma unroll
        for (int j = 0; j < 4; j++) wmma::fill_fragment(c[i][j], 0.f);

    #pragma unroll
    for (int k = 0; k < 8; k++) {
        wmma::fragment<wmma::matrix_a, 16, 16, 16, __half, wmma::row_major> a[2];
        wmma::fragment<wmma::matrix_b, 16, 16, 16, __half, wmma::row_major> b[4];
        #pragma unroll
        for (int i = 0; i < 2; i++)
            wmma::load_matrix_sync(a[i], &A[(base + 32 * wr + 16 * i) * F + 16 * k], F);
        #pragma unroll
        for (int j = 0; j < 4; j++)
            wmma::load_matrix_sync(b[j], &B[16 * k * F + 64 * wc + 16 * j], F);
        #pragma unroll
        for (int i = 0; i < 2; i++)
            #pragma unroll
            for (int j = 0; j < 4; j++)
                wmma::mma_sync(c[i][j], a[i], b[j], c[i][j]);
    }

    #pragma unroll
    for (int i = 0; i < 2; i++)
        #pragma unroll
        for (int j = 0; j < 4; j++)
            wmma::store_matrix_sync(
                &g_feat[(base + 32 * wr + 16 * i) * F + 64 * wc + 16 * j],
                c[i][j], F, wmma::mem_row_major);
}

// ---------------- fused softmax + aggregation (+ next-layer wprep) ---------
// One warp per dst node, cooperative weights, fp32 float4 gather. Writes
// fp32 h out AND its fp16 copy (next layer's MMA operand). No softmax shift.
__global__ __launch_bounds__(256) void gat_agg_kernel(
    const int* __restrict__ src,
    const float* __restrict__ hres,
    float* __restrict__ out,
    int slot, int do_act, int do_mean,
    const float* __restrict__ Wn, const float* __restrict__ aln,
    const float* __restrict__ arn)
{
    if (blockIdx.x == AGG_GRID) {            // tail block: next layer's wprep
        if (Wn) wprep_dev(Wn, aln, arn, slot + 1);
        return;
    }
    const int gw = (blockIdx.x * blockDim.x + threadIdx.x) >> 5;
    if (gw >= NN) return;
    const int lane = threadIdx.x & 31;
    const int n = gw;
    const int e0 = g_rowptr[n];
    const int e1 = g_rowptr[n + 1];
    const int g = lane >> 3;          // head owned by this lane
    const int p = lane & 7;
    const int shfl_base = lane & 24;
    const float ern = g_er[n * 4 + g];

    float ssum = 0.f;
    float4 acc = make_float4(0.f, 0.f, 0.f, 0.f);
    const float4* feat4 = reinterpret_cast<const float4*>(g_feat);

    for (int basee = e0; basee < e1; basee += 32) {
        int idx = basee + lane;
        int sw = (idx < e1) ? __ldg(&src[idx]) : 0;

        // cooperative weights: wv[k] = weight of edge basee+8k+p at head g
        float wv[4];
        #pragma unroll
        for (int k = 0; k < 4; k++) {
            int jj = 8 * k + p;
            int s = __shfl_sync(0xffffffffu, sw, jj);
            float e = __ldg(&g_el[s * 4 + g]) + ern;
            e = (e > 0.f) ? e : 0.2f * e;              // leaky_relu(0.2)
            float wgt = __expf(e);
            wgt = (basee + jj < e1) ? wgt : 0.f;
            wv[k] = wgt;
            ssum += wgt;
        }

        // gather-accumulate (bounds warp-uniform -> shfl-safe)
        #pragma unroll
        for (int k = 0; k < 4; k++) {
            if (basee + 8 * k >= e1) break;
            #pragma unroll
            for (int p2 = 0; p2 < 8; p2++) {
                int jj = 8 * k + p2;
                int s = __shfl_sync(0xffffffffu, sw, jj);
                float wgt = __shfl_sync(0xffffffffu, wv[k], shfl_base + p2);
                float4 f = __ldg(&feat4[s * 32 + lane]);
                acc.x = fmaf(wgt, f.x, acc.x);
                acc.y = fmaf(wgt, f.y, acc.y);
                acc.z = fmaf(wgt, f.z, acc.z);
                acc.w = fmaf(wgt, f.w, acc.w);
            }
        }
    }

    // group-reduce ssum across the 8 lanes of this head
    ssum += __shfl_xor_sync(0xffffffffu, ssum, 1);
    ssum += __shfl_xor_sync(0xffffffffu, ssum, 2);
    ssum += __shfl_xor_sync(0xffffffffu, ssum, 4);

    float inv = (e1 > e0) ? (1.f / ssum) : 0.f;
    float4 o = make_float4(acc.x * inv, acc.y * inv, acc.z * inv, acc.w * inv);

    if (hres) {
        float4 rr = __ldg(&reinterpret_cast<const float4*>(hres)[n * 32 + lane]);
        o.x += rr.x; o.y += rr.y; o.z += rr.z; o.w += rr.w;
    }
    if (do_act) {  // ELU(alpha=1)
        o.x = (o.x > 0.f) ? o.x : expm1f(o.x);
        o.y = (o.y > 0.f) ? o.y : expm1f(o.y);
        o.z = (o.z > 0.f) ? o.z : expm1f(o.z);
        o.w = (o.w > 0.f) ? o.w : expm1f(o.w);
    }

    if (do_mean) {
        o.x += __shfl_xor_sync(0xffffffffu, o.x, 8);
        o.y += __shfl_xor_sync(0xffffffffu, o.y, 8);
        o.z += __shfl_xor_sync(0xffffffffu, o.z, 8);
        o.w += __shfl_xor_sync(0xffffffffu, o.w, 8);
        o.x += __shfl_xor_sync(0xffffffffu, o.x, 16);
        o.y += __shfl_xor_sync(0xffffffffu, o.y, 16);
        o.z += __shfl_xor_sync(0xffffffffu, o.z, 16);
        o.w += __shfl_xor_sync(0xffffffffu, o.w, 16);
        if (lane < 8) {
            reinterpret_cast<float4*>(out)[n * 8 + lane] =
                make_float4(o.x * 0.25f, o.y * 0.25f, o.z * 0.25f, o.w * 0.25f);
        }
    } else {
        reinterpret_cast<float4*>(out)[n * 32 + lane] = o;
        // fp16 copy for the next layer's MMA operand
        __half2 q01 = __floats2half2_rn(o.x, o.y);
        __half2 q23 = __floats2half2_rn(o.z, o.w);
        uint2 qk;
        qk.x = *reinterpret_cast<unsigned*>(&q01);
        qk.y = *reinterpret_cast<unsigned*>(&q23);
        reinterpret_cast<uint2*>(g_hin16)[n * 32 + lane] = qk;
    }
}

// ---------------- launcher --------------------------------------------------
extern "C" void kernel_launch(void* const* d_in, const int* in_sizes, int n_in,
                              void* d_out, int out_size)
{
    const float* x   = (const float*)d_in[0];
    const int*   src = (const int*)d_in[1];
    const int*   dst = (const int*)d_in[2];
    const float* W0  = (const float*)d_in[3];
    const float* al0 = (const float*)d_in[4];
    const float* ar0 = (const float*)d_in[5];
    const float* W1  = (const float*)d_in[6];
    const float* al1 = (const float*)d_in[7];
    const float* ar1 = (const float*)d_in[8];
    const float* W2  = (const float*)d_in[9];
    const float* al2 = (const float*)d_in[10];
    const float* ar2 = (const float*)d_in[11];
    float* out = (float*)d_out;

    float *h1 = nullptr, *h2 = nullptr;
    cudaGetSymbolAddress((void**)&h1, g_h1);
    cudaGetSymbolAddress((void**)&h2, g_h2);

    const int scores_smem = F * SPAD * (int)sizeof(float);   // 33280 B
    const int ms_grid = MMA_GRID + SCORES_GRID;              // 1173
    const int rp_grid = 196 + 1 + (NP / 64);                 // 196+1+782

    rowptr_kernel<<<rp_grid, 256>>>(dst, x, W0, al0, ar0);

    // layer 0 (agg tail-block preps layer 1)
    mma_scores_kernel<<<ms_grid, 256, scores_smem>>>(x, 0);
    gat_agg_kernel<<<AGG_GRID + 1, 256>>>(src, nullptr, h1, 0, 1, 0, W1, al1, ar1);

    // layer 1 (agg tail-block preps layer 2)
    mma_scores_kernel<<<ms_grid, 256, scores_smem>>>(h1, 1);
    gat_agg_kernel<<<AGG_GRID + 1, 256>>>(src, h1, h2, 1, 1, 0, W2, al2, ar2);

    // layer 2 (mean over heads)
    mma_scores_kernel<<<ms_grid, 256, scores_smem>>>(h2, 2);
    gat_agg_kernel<<<AGG_GRID + 1, 256>>>(src, h2, out, 2, 0, 1,
                                          nullptr, nullptr, nullptr);
}

// round 15
// speedup vs baseline: 1.2240x; 1.2240x over previous
#include <cuda_runtime.h>
#include <cuda_fp16.h>
#include <mma.h>
#include <math.h>
#include <stdint.h>

using namespace nvcuda;

#define NN 50000
#define NP 50048      // padded rows (mult of 128) for unguarded C stores
#define NE 800000
#define F  128
#define MT 128        // rows per MMA block
#define HLD 136       // half leading dim for A/B smem
#define SPAD 65       // scores transposed-tile pad
#define MMA_GRID    391
#define SCORES_GRID 782
#define AGG_GRID   6250

// ---------------- scratch (device globals; no allocation allowed) ----------
__device__ __align__(16) float g_feat[NP * F];   // fp32 GEMM output (padded)
__device__ __align__(16) float g_h1[NN * F];
__device__ __align__(16) float g_h2[NN * F];
__device__ __align__(16) float g_el[NN * 4];
__device__ __align__(16) float g_er[NN * 4];
__device__ __align__(16) float g_wl[3][4 * F];   // W @ al[h]
__device__ __align__(16) float g_wr[3][4 * F];   // W @ ar[h]
__device__ int g_rowptr[NN + 1];

// ---------------- wprep: wl[h]=W@al[h], wr[h]=W@ar[h] (exact fp32) ---------
__device__ __forceinline__ void wprep_dev(
    const float* __restrict__ W, const float* __restrict__ al,
    const float* __restrict__ ar, int slot)
{
    const int tid = threadIdx.x;
    #pragma unroll
    for (int j = 0; j < 4; j++) {
        int o = tid + 256 * j;                 // 1024 outputs
        int k = o & 127, hh = o >> 7, h = hh & 3;
        const float* vec = (hh < 4) ? al : ar;
        float s = 0.f;
        #pragma unroll
        for (int d = 0; d < 32; d++)
            s = fmaf(__ldg(&W[k * F + h * 32 + d]), __ldg(&vec[h * 32 + d]), s);
        if (hh < 4) g_wl[slot][h * F + k] = s; else g_wr[slot][h * F + k] = s;
    }
}

// ---------------- row_ptr (sorted dst) + layer-0 wprep ---------------------
__global__ void rowptr_kernel(const int* __restrict__ dst,
                              const float* __restrict__ W0,
                              const float* __restrict__ al0,
                              const float* __restrict__ ar0)
{
    if (blockIdx.x == gridDim.x - 1) { wprep_dev(W0, al0, ar0, 0); return; }
    int n = blockIdx.x * blockDim.x + threadIdx.x;
    if (n > NN) return;
    int lo = 0, hi = NE;
    while (lo < hi) {
        int mid = (lo + hi) >> 1;
        if (dst[mid] < n) lo = mid + 1; else hi = mid;
    }
    g_rowptr[n] = lo;
}

// ---------------- fused MMA (fp16 WMMA, staged) + scores (exact fp32) ------
// Blocks [0, MMA_GRID): 128x128 feat tile; C frags stored DIRECTLY to padded
// global g_feat (no smem C staging, no epilogue barriers).
// Blocks [MMA_GRID, ..): 64 rows of el/er from wl/wr.
extern __shared__ __align__(16) char s_raw[];

__global__ __launch_bounds__(256) void mma_scores_kernel(
    const float* __restrict__ hin, const float* __restrict__ W, int slot)
{
    const int tid = threadIdx.x;

    if (blockIdx.x >= MMA_GRID) {
        // ================= scores path =================
        float* hsT = reinterpret_cast<float*>(s_raw);   // [F][SPAD]
        const int base = (blockIdx.x - MMA_GRID) * 64;
        {
            const int k4 = tid & 31, r0 = tid >> 5;
            #pragma unroll
            for (int j = 0; j < 8; j++) {
                int r = r0 + 8 * j;
                int n = base + r;
                float4 v = (n < NN)
                    ? __ldg(reinterpret_cast<const float4*>(&hin[n * F + 4 * k4]))
                    : make_float4(0.f, 0.f, 0.f, 0.f);
                hsT[(4 * k4 + 0) * SPAD + r] = v.x;
                hsT[(4 * k4 + 1) * SPAD + r] = v.y;
                hsT[(4 * k4 + 2) * SPAD + r] = v.z;
                hsT[(4 * k4 + 3) * SPAD + r] = v.w;
            }
        }
        __syncthreads();

        const int r  = tid & 63;
        const int hd = tid >> 6;
        const int n  = base + r;
        float el = 0.f, er = 0.f;
        const float4* wl4 = reinterpret_cast<const float4*>(g_wl[slot]);
        const float4* wr4 = reinterpret_cast<const float4*>(g_wr[slot]);
        #pragma unroll 8
        for (int k4 = 0; k4 < 32; k4++) {
            float4 wlv = __ldg(&wl4[hd * 32 + k4]);
            float4 wrv = __ldg(&wr4[hd * 32 + k4]);
            float h0 = hsT[(4 * k4 + 0) * SPAD + r];
            float h1 = hsT[(4 * k4 + 1) * SPAD + r];
            float h2 = hsT[(4 * k4 + 2) * SPAD + r];
            float h3 = hsT[(4 * k4 + 3) * SPAD + r];
            el = fmaf(h0, wlv.x, fmaf(h1, wlv.y, fmaf(h2, wlv.z, fmaf(h3, wlv.w, el))));
            er = fmaf(h0, wrv.x, fmaf(h1, wrv.y, fmaf(h2, wrv.z, fmaf(h3, wrv.w, er))));
        }
        if (n < NN) {
            g_el[n * 4 + hd] = el;
            g_er[n * 4 + hd] = er;
        }
        return;
    }

    // ================= MMA path =================
    __half* As = reinterpret_cast<__half*>(s_raw);               // [128][HLD]
    __half* Bs = reinterpret_cast<__half*>(s_raw) + MT * HLD;    // [128][HLD]
    const int base = blockIdx.x * MT;

    #pragma unroll
    for (int i = 0; i < 16; i++) {
        int idx = tid + 256 * i;
        int row = idx >> 5, c4 = idx & 31;
        int n = base + row;
        float4 v = (n < NN)
            ? __ldg(reinterpret_cast<const float4*>(&hin[n * F + 4 * c4]))
            : make_float4(0.f, 0.f, 0.f, 0.f);
        __half2 a01 = __floats2half2_rn(v.x, v.y);
        __half2 a23 = __floats2half2_rn(v.z, v.w);
        uint2 pa;
        pa.x = *reinterpret_cast<unsigned*>(&a01);
        pa.y = *reinterpret_cast<unsigned*>(&a23);
        *reinterpret_cast<uint2*>(&As[row * HLD + 4 * c4]) = pa;

        float4 wv = __ldg(reinterpret_cast<const float4*>(&W[idx * 4]));
        __half2 b01 = __floats2half2_rn(wv.x, wv.y);
        __half2 b23 = __floats2half2_rn(wv.z, wv.w);
        uint2 pb;
        pb.x = *reinterpret_cast<unsigned*>(&b01);
        pb.y = *reinterpret_cast<unsigned*>(&b23);
        *reinterpret_cast<uint2*>(&Bs[row * HLD + 4 * c4]) = pb;
    }
    __syncthreads();

    const int w  = tid >> 5;
    const int wr = w & 3;       // rows 32*wr .. +31
    const int wc = w >> 2;      // cols 64*wc .. +63

    wmma::fragment<wmma::accumulator, 16, 16, 16, float> c[2][4];
    #pragma unroll
    for (int i = 0; i < 2; i++)
        #pragma unroll
        for (int j = 0; j < 4; j++) wmma::fill_fragment(c[i][j], 0.f);

    #pragma unroll
    for (int k = 0; k < 8; k++) {
        wmma::fragment<wmma::matrix_a, 16, 16, 16, __half, wmma::row_major> a[2];
        wmma::fragment<wmma::matrix_b, 16, 16, 16, __half, wmma::row_major> b[4];
        #pragma unroll
        for (int i = 0; i < 2; i++)
            wmma::load_matrix_sync(a[i], &As[(32 * wr + 16 * i) * HLD + 16 * k], HLD);
        #pragma unroll
        for (int j = 0; j < 4; j++)
            wmma::load_matrix_sync(b[j], &Bs[16 * k * HLD + 64 * wc + 16 * j], HLD);
        #pragma unroll
        for (int i = 0; i < 2; i++)
            #pragma unroll
            for (int j = 0; j < 4; j++)
                wmma::mma_sync(c[i][j], a[i], b[j], c[i][j]);
    }

    // ---- direct global C store (padded rows -> no bounds check) ----
    #pragma unroll
    for (int i = 0; i < 2; i++)
        #pragma unroll
        for (int j = 0; j < 4; j++)
            wmma::store_matrix_sync(
                &g_feat[(base + 32 * wr + 16 * i) * F + 64 * wc + 16 * j],
                c[i][j], F, wmma::mem_row_major);
}

// ---------------- fused softmax + aggregation (+ next-layer wprep) ---------
// One warp per dst node, cooperative weights (4x/window score math), fp32
// float4 gather. No softmax shift (shift-invariant; |scores| small).
__global__ __launch_bounds__(256) void gat_agg_kernel(
    const int* __restrict__ src,
    const float* __restrict__ hres,
    float* __restrict__ out,
    int slot, int do_act, int do_mean,
    const float* __restrict__ Wn, const float* __restrict__ aln,
    const float* __restrict__ arn)
{
    if (blockIdx.x == AGG_GRID) {            // tail block: next layer's wprep
        if (Wn) wprep_dev(Wn, aln, arn, slot + 1);
        return;
    }
    const int gw = (blockIdx.x * blockDim.x + threadIdx.x) >> 5;
    if (gw >= NN) return;
    const int lane = threadIdx.x & 31;
    const int n = gw;
    const int e0 = g_rowptr[n];
    const int e1 = g_rowptr[n + 1];
    const int g = lane >> 3;          // head owned by this lane
    const int p = lane & 7;
    const int shfl_base = lane & 24;
    const float ern = g_er[n * 4 + g];

    float ssum = 0.f;
    float4 acc = make_float4(0.f, 0.f, 0.f, 0.f);
    const float4* feat4 = reinterpret_cast<const float4*>(g_feat);

    for (int basee = e0; basee < e1; basee += 32) {
        int idx = basee + lane;
        int sw = (idx < e1) ? __ldg(&src[idx]) : 0;

        // cooperative weights: wv[k] = weight of edge basee+8k+p at head g
        float wv[4];
        #pragma unroll
        for (int k = 0; k < 4; k++) {
            int jj = 8 * k + p;
            int s = __shfl_sync(0xffffffffu, sw, jj);
            float e = __ldg(&g_el[s * 4 + g]) + ern;
            e = (e > 0.f) ? e : 0.2f * e;              // leaky_relu(0.2)
            float wgt = __expf(e);
            wgt = (basee + jj < e1) ? wgt : 0.f;
            wv[k] = wgt;
            ssum += wgt;
        }

        // gather-accumulate (bounds warp-uniform -> shfl-safe)
        #pragma unroll
        for (int k = 0; k < 4; k++) {
            if (basee + 8 * k >= e1) break;
            #pragma unroll
            for (int p2 = 0; p2 < 8; p2++) {
                int jj = 8 * k + p2;
                int s = __shfl_sync(0xffffffffu, sw, jj);
                float wgt = __shfl_sync(0xffffffffu, wv[k], shfl_base + p2);
                float4 f = __ldg(&feat4[s * 32 + lane]);
                acc.x = fmaf(wgt, f.x, acc.x);
                acc.y = fmaf(wgt, f.y, acc.y);
                acc.z = fmaf(wgt, f.z, acc.z);
                acc.w = fmaf(wgt, f.w, acc.w);
            }
        }
    }

    // group-reduce ssum across the 8 lanes of this head
    ssum += __shfl_xor_sync(0xffffffffu, ssum, 1);
    ssum += __shfl_xor_sync(0xffffffffu, ssum, 2);
    ssum += __shfl_xor_sync(0xffffffffu, ssum, 4);

    float inv = (e1 > e0) ? (1.f / ssum) : 0.f;
    float4 o = make_float4(acc.x * inv, acc.y * inv, acc.z * inv, acc.w * inv);

    if (hres) {
        float4 rr = __ldg(&reinterpret_cast<const float4*>(hres)[n * 32 + lane]);
        o.x += rr.x; o.y += rr.y; o.z += rr.z; o.w += rr.w;
    }
    if (do_act) {  // ELU(alpha=1)
        o.x = (o.x > 0.f) ? o.x : expm1f(o.x);
        o.y = (o.y > 0.f) ? o.y : expm1f(o.y);
        o.z = (o.z > 0.f) ? o.z : expm1f(o.z);
        o.w = (o.w > 0.f) ? o.w : expm1f(o.w);
    }

    if (do_mean) {
        o.x += __shfl_xor_sync(0xffffffffu, o.x, 8);
        o.y += __shfl_xor_sync(0xffffffffu, o.y, 8);
        o.z += __shfl_xor_sync(0xffffffffu, o.z, 8);
        o.w += __shfl_xor_sync(0xffffffffu, o.w, 8);
        o.x += __shfl_xor_sync(0xffffffffu, o.x, 16);
        o.y += __shfl_xor_sync(0xffffffffu, o.y, 16);
        o.z += __shfl_xor_sync(0xffffffffu, o.z, 16);
        o.w += __shfl_xor_sync(0xffffffffu, o.w, 16);
        if (lane < 8) {
            reinterpret_cast<float4*>(out)[n * 8 + lane] =
                make_float4(o.x * 0.25f, o.y * 0.25f, o.z * 0.25f, o.w * 0.25f);
        }
    } else {
        reinterpret_cast<float4*>(out)[n * 32 + lane] = o;
    }
}

// ---------------- launcher --------------------------------------------------
extern "C" void kernel_launch(void* const* d_in, const int* in_sizes, int n_in,
                              void* d_out, int out_size)
{
    const float* x   = (const float*)d_in[0];
    const int*   src = (const int*)d_in[1];
    const int*   dst = (const int*)d_in[2];
    const float* W0  = (const float*)d_in[3];
    const float* al0 = (const float*)d_in[4];
    const float* ar0 = (const float*)d_in[5];
    const float* W1  = (const float*)d_in[6];
    const float* al1 = (const float*)d_in[7];
    const float* ar1 = (const float*)d_in[8];
    const float* W2  = (const float*)d_in[9];
    const float* al2 = (const float*)d_in[10];
    const float* ar2 = (const float*)d_in[11];
    float* out = (float*)d_out;

    float *h1 = nullptr, *h2 = nullptr;
    cudaGetSymbolAddress((void**)&h1, g_h1);
    cudaGetSymbolAddress((void**)&h2, g_h2);

    const int mma_smem = 2 * MT * HLD * (int)sizeof(__half);  // 69632 B
    static int smem_set = 0;
    if (!smem_set) {
        cudaFuncSetAttribute(mma_scores_kernel,
                             cudaFuncAttributeMaxDynamicSharedMemorySize, mma_smem);
        smem_set = 1;
    }

    const int ms_grid = MMA_GRID + SCORES_GRID;      // 1173
    const int rp_grid = (NN + 1 + 255) / 256 + 1;    // rowptr + wprep0

    rowptr_kernel<<<rp_grid, 256>>>(dst, W0, al0, ar0);

    // layer 0 (agg tail-block preps layer 1)
    mma_scores_kernel<<<ms_grid, 256, mma_smem>>>(x, W0, 0);
    gat_agg_kernel<<<AGG_GRID + 1, 256>>>(src, nullptr, h1, 0, 1, 0, W1, al1, ar1);

    // layer 1 (agg tail-block preps layer 2)
    mma_scores_kernel<<<ms_grid, 256, mma_smem>>>(h1, W1, 1);
    gat_agg_kernel<<<AGG_GRID + 1, 256>>>(src, h1, h2, 1, 1, 0, W2, al2, ar2);

    // layer 2 (mean over heads)
    mma_scores_kernel<<<ms_grid, 256, mma_smem>>>(h2, W2, 2);
    gat_agg_kernel<<<AGG_GRID + 1, 256>>>(src, h2, out, 2, 0, 1,
                                          nullptr, nullptr, nullptr);
}

// round 16
// speedup vs baseline: 1.6239x; 1.3267x over previous
#include <cuda_runtime.h>
#include <cuda_fp16.h>
#include <mma.h>
#include <math.h>
#include <stdint.h>

using namespace nvcuda;

#define NN 50000
#define NE 800000
#define F  128
#define MT 128        // rows per MMA block
#define HLD 136       // half leading dim for A/B smem
#define CLD 132       // float leading dim for C staging
#define SPAD 65       // scores transposed-tile pad
#define MMA_GRID    391
#define SCORES_GRID 782
#define AGG_GRID   6250

// ---------------- scratch (device globals; no allocation allowed) ----------
__device__ __align__(16) __half g_feath[NN * F];
__device__ __align__(16) float g_h1[NN * F];
__device__ __align__(16) float g_h2[NN * F];
__device__ __align__(16) float g_el[2][NN * 4];   // double-buffered scores
__device__ __align__(16) float g_er[2][NN * 4];
__device__ __align__(16) float g_wl[3][4 * F];    // W @ al[h], per layer
__device__ __align__(16) float g_wr[3][4 * F];    // W @ ar[h]
__device__ int g_rowptr[NN + 1];

// ---------------- wprep: wl[h]=W@al[h], wr[h]=W@ar[h] (exact fp32) ---------
__device__ __forceinline__ void wprep_dev(
    const float* __restrict__ W, const float* __restrict__ al,
    const float* __restrict__ ar, int slot)
{
    const int tid = threadIdx.x;
    #pragma unroll
    for (int j = 0; j < 4; j++) {
        int o = tid + 256 * j;                 // 1024 outputs
        int k = o & 127, hh = o >> 7, h = hh & 3;
        const float* vec = (hh < 4) ? al : ar;
        float s = 0.f;
        #pragma unroll
        for (int d = 0; d < 32; d++)
            s = fmaf(__ldg(&W[k * F + h * 32 + d]), __ldg(&vec[h * 32 + d]), s);
        if (hh < 4) g_wl[slot][h * F + k] = s; else g_wr[slot][h * F + k] = s;
    }
}

// ---------------- row_ptr (sorted dst) + wprep for ALL 3 layers ------------
__global__ void rowptr_kernel(const int* __restrict__ dst,
                              const float* __restrict__ W0,
                              const float* __restrict__ al0,
                              const float* __restrict__ ar0,
                              const float* __restrict__ W1,
                              const float* __restrict__ al1,
                              const float* __restrict__ ar1,
                              const float* __restrict__ W2,
                              const float* __restrict__ al2,
                              const float* __restrict__ ar2)
{
    if (blockIdx.x >= 196) {
        int s = blockIdx.x - 196;
        if (s == 0) wprep_dev(W0, al0, ar0, 0);
        else if (s == 1) wprep_dev(W1, al1, ar1, 1);
        else wprep_dev(W2, al2, ar2, 2);
        return;
    }
    int n = blockIdx.x * blockDim.x + threadIdx.x;
    if (n > NN) return;
    int lo = 0, hi = NE;
    while (lo < hi) {
        int mid = (lo + hi) >> 1;
        if (dst[mid] < n) lo = mid + 1; else hi = mid;
    }
    g_rowptr[n] = lo;
}

// ---------------- fused MMA (fp16 WMMA, staged) [+ scores for layer 0] -----
// Blocks [0, MMA_GRID): 128x128 feat tile, fp16 writeout (R13 path).
// Blocks beyond (layer 0 only): 64 rows of el/er from x into buffer ebuf.
extern __shared__ __align__(16) char s_raw[];

__global__ __launch_bounds__(256) void mma_scores_kernel(
    const float* __restrict__ hin, const float* __restrict__ W,
    int slot, int ebuf)
{
    const int tid = threadIdx.x;

    if (blockIdx.x >= MMA_GRID) {
        // ================= scores path (layer 0 only) =================
        float* hsT = reinterpret_cast<float*>(s_raw);   // [F][SPAD]
        const int base = (blockIdx.x - MMA_GRID) * 64;
        {
            const int k4 = tid & 31, r0 = tid >> 5;
            #pragma unroll
            for (int j = 0; j < 8; j++) {
                int r = r0 + 8 * j;
                int n = base + r;
                float4 v = (n < NN)
                    ? __ldg(reinterpret_cast<const float4*>(&hin[n * F + 4 * k4]))
                    : make_float4(0.f, 0.f, 0.f, 0.f);
                hsT[(4 * k4 + 0) * SPAD + r] = v.x;
                hsT[(4 * k4 + 1) * SPAD + r] = v.y;
                hsT[(4 * k4 + 2) * SPAD + r] = v.z;
                hsT[(4 * k4 + 3) * SPAD + r] = v.w;
            }
        }
        __syncthreads();

        const int r  = tid & 63;
        const int hd = tid >> 6;
        const int n  = base + r;
        float el = 0.f, er = 0.f;
        const float4* wl4 = reinterpret_cast<const float4*>(g_wl[slot]);
        const float4* wr4 = reinterpret_cast<const float4*>(g_wr[slot]);
        #pragma unroll 8
        for (int k4 = 0; k4 < 32; k4++) {
            float4 wlv = __ldg(&wl4[hd * 32 + k4]);
            float4 wrv = __ldg(&wr4[hd * 32 + k4]);
            float h0 = hsT[(4 * k4 + 0) * SPAD + r];
            float h1 = hsT[(4 * k4 + 1) * SPAD + r];
            float h2 = hsT[(4 * k4 + 2) * SPAD + r];
            float h3 = hsT[(4 * k4 + 3) * SPAD + r];
            el = fmaf(h0, wlv.x, fmaf(h1, wlv.y, fmaf(h2, wlv.z, fmaf(h3, wlv.w, el))));
            er = fmaf(h0, wrv.x, fmaf(h1, wrv.y, fmaf(h2, wrv.z, fmaf(h3, wrv.w, er))));
        }
        if (n < NN) {
            g_el[ebuf][n * 4 + hd] = el;
            g_er[ebuf][n * 4 + hd] = er;
        }
        return;
    }

    // ================= MMA path (R13: staged, Cs, fp16 out) ================
    __half* As = reinterpret_cast<__half*>(s_raw);               // [128][HLD]
    __half* Bs = reinterpret_cast<__half*>(s_raw) + MT * HLD;    // [128][HLD]
    float*  Cs = reinterpret_cast<float*>(s_raw);                // [128][CLD]
    const int base = blockIdx.x * MT;

    #pragma unroll
    for (int i = 0; i < 16; i++) {
        int idx = tid + 256 * i;
        int row = idx >> 5, c4 = idx & 31;
        int n = base + row;
        float4 v = (n < NN)
            ? __ldg(reinterpret_cast<const float4*>(&hin[n * F + 4 * c4]))
            : make_float4(0.f, 0.f, 0.f, 0.f);
        __half2 a01 = __floats2half2_rn(v.x, v.y);
        __half2 a23 = __floats2half2_rn(v.z, v.w);
        uint2 pa;
        pa.x = *reinterpret_cast<unsigned*>(&a01);
        pa.y = *reinterpret_cast<unsigned*>(&a23);
        *reinterpret_cast<uint2*>(&As[row * HLD + 4 * c4]) = pa;

        float4 wv = __ldg(reinterpret_cast<const float4*>(&W[idx * 4]));
        __half2 b01 = __floats2half2_rn(wv.x, wv.y);
        __half2 b23 = __floats2half2_rn(wv.z, wv.w);
        uint2 pb;
        pb.x = *reinterpret_cast<unsigned*>(&b01);
        pb.y = *reinterpret_cast<unsigned*>(&b23);
        *reinterpret_cast<uint2*>(&Bs[row * HLD + 4 * c4]) = pb;
    }
    __syncthreads();

    const int w  = tid >> 5;
    const int wr = w & 3;       // rows 32*wr .. +31
    const int wc = w >> 2;      // cols 64*wc .. +63

    wmma::fragment<wmma::accumulator, 16, 16, 16, float> c[2][4];
    #pragma unroll
    for (int i = 0; i < 2; i++)
        #pragma unroll
        for (int j = 0; j < 4; j++) wmma::fill_fragment(c[i][j], 0.f);

    #pragma unroll
    for (int k = 0; k < 8; k++) {
        wmma::fragment<wmma::matrix_a, 16, 16, 16, __half, wmma::row_major> a[2];
        wmma::fragment<wmma::matrix_b, 16, 16, 16, __half, wmma::row_major> b[4];
        #pragma unroll
        for (int i = 0; i < 2; i++)
            wmma::load_matrix_sync(a[i], &As[(32 * wr + 16 * i) * HLD + 16 * k], HLD);
        #pragma unroll
        for (int j = 0; j < 4; j++)
            wmma::load_matrix_sync(b[j], &Bs[16 * k * HLD + 64 * wc + 16 * j], HLD);
        #pragma unroll
        for (int i = 0; i < 2; i++)
            #pragma unroll
            for (int j = 0; j < 4; j++)
                wmma::mma_sync(c[i][j], a[i], b[j], c[i][j]);
    }
    __syncthreads();

    #pragma unroll
    for (int i = 0; i < 2; i++)
        #pragma unroll
        for (int j = 0; j < 4; j++)
            wmma::store_matrix_sync(
                &Cs[(32 * wr + 16 * i) * CLD + 64 * wc + 16 * j],
                c[i][j], CLD, wmma::mem_row_major);
    __syncthreads();

    #pragma unroll
    for (int i = 0; i < 16; i++) {
        int idx = tid + 256 * i;
        int row = idx >> 5, c4 = idx & 31;
        int n = base + row;
        if (n < NN) {
            float4 v = *reinterpret_cast<const float4*>(&Cs[row * CLD + 4 * c4]);
            __half2 p01 = __floats2half2_rn(v.x, v.y);
            __half2 p23 = __floats2half2_rn(v.z, v.w);
            uint2 pk;
            pk.x = *reinterpret_cast<unsigned*>(&p01);
            pk.y = *reinterpret_cast<unsigned*>(&p23);
            *reinterpret_cast<uint2*>(&g_feath[n * F + 4 * c4]) = pk;
        }
    }
}

// ---------------- fused softmax + aggregation + next-layer scores ----------
// One warp per dst node, cooperative weights, fp16 gather. Reads el/er from
// buffer rbuf; epilogue computes next layer's el/er from the in-register
// output and writes them to buffer rbuf^1 (skipped on the mean layer).
__global__ __launch_bounds__(256) void gat_agg_kernel(
    const int* __restrict__ src,
    const float* __restrict__ hres,
    float* __restrict__ out,
    int rbuf, int nslot, int do_act, int do_mean)
{
    const int gw = (blockIdx.x * blockDim.x + threadIdx.x) >> 5;
    if (gw >= NN) return;
    const int lane = threadIdx.x & 31;
    const int n = gw;
    const int e0 = g_rowptr[n];
    const int e1 = g_rowptr[n + 1];
    const int g = lane >> 3;
    const int p = lane & 7;
    const int shfl_base = lane & 24;
    const float* elr = g_el[rbuf];
    const float ern = g_er[rbuf][n * 4 + g];

    float ssum = 0.f;
    float4 acc = make_float4(0.f, 0.f, 0.f, 0.f);
    const uint2* feat8 = reinterpret_cast<const uint2*>(g_feath);

    for (int basee = e0; basee < e1; basee += 32) {
        int idx = basee + lane;
        int sw = (idx < e1) ? __ldg(&src[idx]) : 0;

        float wv[4];
        #pragma unroll
        for (int k = 0; k < 4; k++) {
            int jj = 8 * k + p;
            int s = __shfl_sync(0xffffffffu, sw, jj);
            float e = __ldg(&elr[s * 4 + g]) + ern;
            e = (e > 0.f) ? e : 0.2f * e;              // leaky_relu(0.2)
            float wgt = __expf(e);
            wgt = (basee + jj < e1) ? wgt : 0.f;
            wv[k] = wgt;
            ssum += wgt;
        }

        #pragma unroll
        for (int k = 0; k < 4; k++) {
            if (basee + 8 * k >= e1) break;
            #pragma unroll
            for (int p2 = 0; p2 < 8; p2++) {
                int jj = 8 * k + p2;
                int s = __shfl_sync(0xffffffffu, sw, jj);
                float wgt = __shfl_sync(0xffffffffu, wv[k], shfl_base + p2);
                uint2 pk = __ldg(&feat8[s * 32 + lane]);
                float2 f01 = __half22float2(*reinterpret_cast<__half2*>(&pk.x));
                float2 f23 = __half22float2(*reinterpret_cast<__half2*>(&pk.y));
                acc.x = fmaf(wgt, f01.x, acc.x);
                acc.y = fmaf(wgt, f01.y, acc.y);
                acc.z = fmaf(wgt, f23.x, acc.z);
                acc.w = fmaf(wgt, f23.y, acc.w);
            }
        }
    }

    ssum += __shfl_xor_sync(0xffffffffu, ssum, 1);
    ssum += __shfl_xor_sync(0xffffffffu, ssum, 2);
    ssum += __shfl_xor_sync(0xffffffffu, ssum, 4);

    float inv = (e1 > e0) ? (1.f / ssum) : 0.f;
    float4 o = make_float4(acc.x * inv, acc.y * inv, acc.z * inv, acc.w * inv);

    if (hres) {
        float4 rr = __ldg(&reinterpret_cast<const float4*>(hres)[n * 32 + lane]);
        o.x += rr.x; o.y += rr.y; o.z += rr.z; o.w += rr.w;
    }
    if (do_act) {  // ELU(alpha=1)
        o.x = (o.x > 0.f) ? o.x : expm1f(o.x);
        o.y = (o.y > 0.f) ? o.y : expm1f(o.y);
        o.z = (o.z > 0.f) ? o.z : expm1f(o.z);
        o.w = (o.w > 0.f) ? o.w : expm1f(o.w);
    }

    if (do_mean) {
        o.x += __shfl_xor_sync(0xffffffffu, o.x, 8);
        o.y += __shfl_xor_sync(0xffffffffu, o.y, 8);
        o.z += __shfl_xor_sync(0xffffffffu, o.z, 8);
        o.w += __shfl_xor_sync(0xffffffffu, o.w, 8);
        o.x += __shfl_xor_sync(0xffffffffu, o.x, 16);
        o.y += __shfl_xor_sync(0xffffffffu, o.y, 16);
        o.z += __shfl_xor_sync(0xffffffffu, o.z, 16);
        o.w += __shfl_xor_sync(0xffffffffu, o.w, 16);
        if (lane < 8) {
            reinterpret_cast<float4*>(out)[n * 8 + lane] =
                make_float4(o.x * 0.25f, o.y * 0.25f, o.z * 0.25f, o.w * 0.25f);
        }
        return;
    }

    reinterpret_cast<float4*>(out)[n * 32 + lane] = o;

    // ---- epilogue: next-layer el/er from in-register output ----
    {
        const float4* wl4 = reinterpret_cast<const float4*>(g_wl[nslot]);
        const float4* wr4 = reinterpret_cast<const float4*>(g_wr[nslot]);
        float pel[4], per_[4];
        #pragma unroll
        for (int h = 0; h < 4; h++) {
            float4 a = __ldg(&wl4[h * 32 + lane]);
            pel[h] = fmaf(o.x, a.x, fmaf(o.y, a.y, fmaf(o.z, a.z, o.w * a.w)));
            float4 b = __ldg(&wr4[h * 32 + lane]);
            per_[h] = fmaf(o.x, b.x, fmaf(o.y, b.y, fmaf(o.z, b.z, o.w * b.w)));
        }
        #pragma unroll
        for (int off = 16; off > 0; off >>= 1) {
            #pragma unroll
            for (int h = 0; h < 4; h++) {
                pel[h] += __shfl_xor_sync(0xffffffffu, pel[h], off);
                per_[h] += __shfl_xor_sync(0xffffffffu, per_[h], off);
            }
        }
        if (lane == 0) {
            int wbuf = rbuf ^ 1;
            *reinterpret_cast<float4*>(&g_el[wbuf][n * 4]) =
                make_float4(pel[0], pel[1], pel[2], pel[3]);
            *reinterpret_cast<float4*>(&g_er[wbuf][n * 4]) =
                make_float4(per_[0], per_[1], per_[2], per_[3]);
        }
    }
}

// ---------------- launcher --------------------------------------------------
extern "C" void kernel_launch(void* const* d_in, const int* in_sizes, int n_in,
                              void* d_out, int out_size)
{
    const float* x   = (const float*)d_in[0];
    const int*   src = (const int*)d_in[1];
    const int*   dst = (const int*)d_in[2];
    const float* W0  = (const float*)d_in[3];
    const float* al0 = (const float*)d_in[4];
    const float* ar0 = (const float*)d_in[5];
    const float* W1  = (const float*)d_in[6];
    const float* al1 = (const float*)d_in[7];
    const float* ar1 = (const float*)d_in[8];
    const float* W2  = (const float*)d_in[9];
    const float* al2 = (const float*)d_in[10];
    const float* ar2 = (const float*)d_in[11];
    float* out = (float*)d_out;

    float *h1 = nullptr, *h2 = nullptr;
    cudaGetSymbolAddress((void**)&h1, g_h1);
    cudaGetSymbolAddress((void**)&h2, g_h2);

    const int mma_smem = 2 * MT * HLD * (int)sizeof(__half);  // 69632 B
    static int smem_set = 0;
    if (!smem_set) {
        cudaFuncSetAttribute(mma_scores_kernel,
                             cudaFuncAttributeMaxDynamicSharedMemorySize, mma_smem);
        smem_set = 1;
    }

    rowptr_kernel<<<196 + 3, 256>>>(dst, W0, al0, ar0, W1, al1, ar1, W2, al2, ar2);

    // layer 0: mma + scores(x)->buf0; agg reads buf0, writes buf1 (slot 1)
    mma_scores_kernel<<<MMA_GRID + SCORES_GRID, 256, mma_smem>>>(x, W0, 0, 0);
    gat_agg_kernel<<<AGG_GRID, 256>>>(src, nullptr, h1, 0, 1, 1, 0);

    // layer 1: mma only; agg reads buf1, writes buf0 (slot 2)
    mma_scores_kernel<<<MMA_GRID, 256, mma_smem>>>(h1, W1, 1, 0);
    gat_agg_kernel<<<AGG_GRID, 256>>>(src, h1, h2, 1, 2, 1, 0);

    // layer 2: mma only; agg reads buf0, mean over heads
    mma_scores_kernel<<<MMA_GRID, 256, mma_smem>>>(h2, W2, 2, 0);
    gat_agg_kernel<<<AGG_GRID, 256>>>(src, h2, out, 0, 0, 0, 1);
}